// round 2
// baseline (speedup 1.0000x reference)
#include <cuda_runtime.h>

// ---------------- problem constants ----------------
#define T_STEPS 192
#define B_SZ    128
#define IN_SZ   512
#define R_SZ    1024
#define OUT_SZ  100
#define PS      64
#define BR      (B_SZ * R_SZ)          // 131072
#define SPK_ELEMS (T_STEPS * BR)       // 25165824
#define OUT_ELEMS (B_SZ * OUT_SZ)      // 12800
#define ALPHA 0.9f
#define BETA  0.9f

// ---------------- device scratch (static, allowed) ----------------
__device__ float g_cur[T_STEPS * BR];   // input projection result (+b_in)
__device__ float g_spk[T_STEPS * BR];   // spike history (floats, 0/1)
__device__ float g_syn[BR];
__device__ float g_mem[BR];
__device__ float g_part[8 * BR];        // split-K partials
__device__ float g_ro[B_SZ * 3 * R_SZ]; // readout input

typedef unsigned long long ull;

__device__ __forceinline__ ull pack2(float lo, float hi) {
    ull r; asm("mov.b64 %0, {%1,%2};" : "=l"(r) : "f"(lo), "f"(hi)); return r;
}
__device__ __forceinline__ void fma2(ull &d, ull a, ull b) {
    asm("fma.rn.f32x2 %0, %1, %2, %0;" : "+l"(d) : "l"(a), "l"(b));
}
__device__ __forceinline__ float2 unpack2(ull v) {
    float2 r; asm("mov.b64 {%0,%1}, %2;" : "=f"(r.x), "=f"(r.y) : "l"(v)); return r;
}

// ---------------- init: zero syn/mem ----------------
__global__ void k_init() {
    int i = blockIdx.x * blockDim.x + threadIdx.x;   // 32768 threads, 4 floats each
    float4 z = make_float4(0.f, 0.f, 0.f, 0.f);
    *(float4*)(g_syn + i * 4) = z;
    *(float4*)(g_mem + i * 4) = z;
}

// ---------------- input projection GEMM ----------------
// cur[t*B+b][r] = sum_i x[t*B+b][i] * W_in[p][r][i] + b_in[r],  p = (t*B+b)/8192
// BM=128, BN=128, BK=16, 256 threads, thread tile 8x8 (f32x2 packed)
__global__ void k_input_gemm(const float* __restrict__ X,
                             const float* __restrict__ Win,
                             const float* __restrict__ bin) {
    __shared__ float As[16][128];
    __shared__ float Bs[16][128];
    int tid = threadIdx.x;
    int n0 = blockIdx.x * 128;
    int m0 = blockIdx.y * 128;
    int p  = m0 >> 13;  // / 8192
    const float* A = X + (size_t)m0 * IN_SZ;
    const float* W = Win + (size_t)p * R_SZ * IN_SZ + (size_t)n0 * IN_SZ;

    int lr = tid >> 2;          // 0..63
    int lk = (tid & 3) * 4;     // 0,4,8,12
    int tx = tid & 15, ty = tid >> 4;

    ull acc[8][4];
#pragma unroll
    for (int i = 0; i < 8; i++)
#pragma unroll
        for (int j = 0; j < 4; j++) acc[i][j] = 0ULL;

    for (int k0 = 0; k0 < IN_SZ; k0 += 16) {
        float4 a0 = *(const float4*)(A + (size_t)lr * IN_SZ + k0 + lk);
        float4 a1 = *(const float4*)(A + (size_t)(lr + 64) * IN_SZ + k0 + lk);
        float4 b0 = *(const float4*)(W + (size_t)lr * IN_SZ + k0 + lk);
        float4 b1 = *(const float4*)(W + (size_t)(lr + 64) * IN_SZ + k0 + lk);
        __syncthreads();
        As[lk + 0][lr] = a0.x; As[lk + 1][lr] = a0.y; As[lk + 2][lr] = a0.z; As[lk + 3][lr] = a0.w;
        As[lk + 0][lr + 64] = a1.x; As[lk + 1][lr + 64] = a1.y; As[lk + 2][lr + 64] = a1.z; As[lk + 3][lr + 64] = a1.w;
        Bs[lk + 0][lr] = b0.x; Bs[lk + 1][lr] = b0.y; Bs[lk + 2][lr] = b0.z; Bs[lk + 3][lr] = b0.w;
        Bs[lk + 0][lr + 64] = b1.x; Bs[lk + 1][lr + 64] = b1.y; Bs[lk + 2][lr + 64] = b1.z; Bs[lk + 3][lr + 64] = b1.w;
        __syncthreads();
#pragma unroll
        for (int kk = 0; kk < 16; kk++) {
            float4 af0 = *(float4*)&As[kk][ty * 8];
            float4 af1 = *(float4*)&As[kk][ty * 8 + 4];
            float4 bf0 = *(float4*)&Bs[kk][tx * 8];
            float4 bf1 = *(float4*)&Bs[kk][tx * 8 + 4];
            ull b2[4] = { pack2(bf0.x, bf0.y), pack2(bf0.z, bf0.w),
                          pack2(bf1.x, bf1.y), pack2(bf1.z, bf1.w) };
            float am[8] = { af0.x, af0.y, af0.z, af0.w, af1.x, af1.y, af1.z, af1.w };
#pragma unroll
            for (int i = 0; i < 8; i++) {
                ull a2 = pack2(am[i], am[i]);
#pragma unroll
                for (int j = 0; j < 4; j++) fma2(acc[i][j], a2, b2[j]);
            }
        }
    }
    float* C = g_cur + (size_t)m0 * R_SZ + n0;
#pragma unroll
    for (int i = 0; i < 8; i++) {
        int m = ty * 8 + i;
#pragma unroll
        for (int j = 0; j < 4; j++) {
            float2 v = unpack2(acc[i][j]);
            int n = tx * 8 + j * 2;
            C[(size_t)m * R_SZ + n]     = v.x + __ldg(bin + n0 + n);
            C[(size_t)m * R_SZ + n + 1] = v.y + __ldg(bin + n0 + n + 1);
        }
    }
}

// ---------------- per-step recurrent GEMM (split-K, dual matrix) ----------------
// Combined K range [0,2048): k<1024 -> spk(t-1)@W_rec^T ; k>=1024 -> spk(t-64)@W_lin^T
// grid (16 n-tiles, 2 m-tiles, 8 K-chunks of 256), BM=BN=64, BK=16, thread tile 4x4
__global__ void k_step_gemm(int t,
                            const float* __restrict__ Wrec,
                            const float* __restrict__ Wlin) {
    int activeK = (t == 0) ? 0 : ((t > PS) ? 2048 : 1024);
    int kbase = blockIdx.z * 256;
    int m0 = blockIdx.y * 64, n0 = blockIdx.x * 64;
    float* Cp = g_part + (size_t)blockIdx.z * BR + (size_t)m0 * R_SZ + n0;
    int tid = threadIdx.x;

    if (kbase >= activeK) {
        for (int i = tid; i < 64 * 64; i += 256) {
            int mm = i >> 6, nn = i & 63;
            Cp[(size_t)mm * R_SZ + nn] = 0.f;
        }
        return;
    }

    const float* A; const float* W; int kofs;
    if (kbase < 1024) { A = g_spk + (size_t)(t - 1) * BR;  W = Wrec; kofs = kbase; }
    else              { A = g_spk + (size_t)(t - PS) * BR; W = Wlin; kofs = kbase - 1024; }
    A += (size_t)m0 * R_SZ + kofs;
    W += (size_t)n0 * R_SZ + kofs;

    __shared__ float As[16][64];
    __shared__ float Bs[16][64];
    int lr = tid >> 2;         // 0..63
    int lk = (tid & 3) * 4;
    int tx = tid & 15, ty = tid >> 4;

    ull acc[4][2];
#pragma unroll
    for (int i = 0; i < 4; i++) { acc[i][0] = 0ULL; acc[i][1] = 0ULL; }

    for (int k0 = 0; k0 < 256; k0 += 16) {
        float4 a = *(const float4*)(A + (size_t)lr * R_SZ + k0 + lk);
        float4 b = *(const float4*)(W + (size_t)lr * R_SZ + k0 + lk);
        __syncthreads();
        As[lk + 0][lr] = a.x; As[lk + 1][lr] = a.y; As[lk + 2][lr] = a.z; As[lk + 3][lr] = a.w;
        Bs[lk + 0][lr] = b.x; Bs[lk + 1][lr] = b.y; Bs[lk + 2][lr] = b.z; Bs[lk + 3][lr] = b.w;
        __syncthreads();
#pragma unroll
        for (int kk = 0; kk < 16; kk++) {
            float4 af = *(float4*)&As[kk][ty * 4];
            float4 bf = *(float4*)&Bs[kk][tx * 4];
            ull b2[2] = { pack2(bf.x, bf.y), pack2(bf.z, bf.w) };
            float am[4] = { af.x, af.y, af.z, af.w };
#pragma unroll
            for (int i = 0; i < 4; i++) {
                ull a2 = pack2(am[i], am[i]);
                fma2(acc[i][0], a2, b2[0]);
                fma2(acc[i][1], a2, b2[1]);
            }
        }
    }
#pragma unroll
    for (int i = 0; i < 4; i++) {
        int m = ty * 4 + i;
#pragma unroll
        for (int j = 0; j < 2; j++) {
            float2 v = unpack2(acc[i][j]);
            int n = tx * 4 + j * 2;
            Cp[(size_t)m * R_SZ + n]     = v.x;
            Cp[(size_t)m * R_SZ + n + 1] = v.y;
        }
    }
}

// ---------------- per-step state update ----------------
__global__ void k_update(int t, float* __restrict__ spk_out,
                         const float* __restrict__ brec) {
    int idx = (blockIdx.x * 256 + threadIdx.x) * 4;  // over BR
    int r = idx & (R_SZ - 1);

    float4 cur = *(const float4*)(g_cur + (size_t)t * BR + idx);
    float4 s = make_float4(0.f, 0.f, 0.f, 0.f);
#pragma unroll
    for (int ks = 0; ks < 8; ks++) {
        float4 pv = *(const float4*)(g_part + (size_t)ks * BR + idx);
        s.x += pv.x; s.y += pv.y; s.z += pv.z; s.w += pv.w;
    }
    float4 br  = *(const float4*)(brec + r);
    float4 syn = *(float4*)(g_syn + idx);
    float4 mem = *(float4*)(g_mem + idx);

    float4 synN, memN, spk;
    {
        synN.x = ALPHA * syn.x + cur.x + s.x + br.x;
        float reset = (mem.x > 1.0f) ? 1.0f : 0.0f;
        memN.x = BETA * mem.x + synN.x - reset;
        spk.x = (memN.x > 1.0f) ? 1.0f : 0.0f;

        synN.y = ALPHA * syn.y + cur.y + s.y + br.y;
        reset = (mem.y > 1.0f) ? 1.0f : 0.0f;
        memN.y = BETA * mem.y + synN.y - reset;
        spk.y = (memN.y > 1.0f) ? 1.0f : 0.0f;

        synN.z = ALPHA * syn.z + cur.z + s.z + br.z;
        reset = (mem.z > 1.0f) ? 1.0f : 0.0f;
        memN.z = BETA * mem.z + synN.z - reset;
        spk.z = (memN.z > 1.0f) ? 1.0f : 0.0f;

        synN.w = ALPHA * syn.w + cur.w + s.w + br.w;
        reset = (mem.w > 1.0f) ? 1.0f : 0.0f;
        memN.w = BETA * mem.w + synN.w - reset;
        spk.w = (memN.w > 1.0f) ? 1.0f : 0.0f;
    }
    *(float4*)(g_syn + idx) = synN;
    *(float4*)(g_mem + idx) = memN;
    *(float4*)(g_spk + (size_t)t * BR + idx) = spk;
    if (spk_out) *(float4*)(spk_out + (size_t)t * BR + idx) = spk;
}

// ---------------- readout mean over each partition ----------------
__global__ void k_ro_reduce() {
    int e = (blockIdx.x * 256 + threadIdx.x) * 4;   // over B*3R = 393216
    int b = e / (3 * R_SZ);
    int c = e % (3 * R_SZ);
    int p = c >> 10;
    int r = c & (R_SZ - 1);
    const float* base = g_spk + ((size_t)(p * PS) * B_SZ + b) * R_SZ + r;
    float4 s = make_float4(0.f, 0.f, 0.f, 0.f);
#pragma unroll 8
    for (int st = 0; st < PS; st++) {
        float4 v = *(const float4*)(base + (size_t)st * BR);
        s.x += v.x; s.y += v.y; s.z += v.z; s.w += v.w;
    }
    float inv = 1.0f / (float)PS;
    s.x *= inv; s.y *= inv; s.z *= inv; s.w *= inv;
    *(float4*)(g_ro + e) = s;
}

// ---------------- final readout GEMM + softmax ----------------
__global__ void k_readout(float* __restrict__ out,
                          const float* __restrict__ Wro,
                          const float* __restrict__ bro) {
    int b = blockIdx.x;
    __shared__ float ro_s[3 * R_SZ];
    __shared__ float logit[112];
    __shared__ float red_sum;
    int tid = threadIdx.x;  // 128 threads

    for (int i = tid * 4; i < 3 * R_SZ; i += 512)
        *(float4*)&ro_s[i] = *(const float4*)(g_ro + (size_t)b * 3 * R_SZ + i);
    __syncthreads();

    int warp = tid >> 5, lane = tid & 31;
    for (int o = warp; o < OUT_SZ; o += 4) {
        const float* w = Wro + (size_t)o * (3 * R_SZ);
        float p0 = 0.f;
        for (int k = lane; k < 3 * R_SZ; k += 32) p0 += ro_s[k] * __ldg(w + k);
#pragma unroll
        for (int off = 16; off; off >>= 1) p0 += __shfl_xor_sync(0xffffffffu, p0, off);
        if (lane == 0) logit[o] = p0 + __ldg(bro + o);
    }
    __syncthreads();
    if (warp == 0) {
        float m = -1e30f;
        for (int i = lane; i < OUT_SZ; i += 32) m = fmaxf(m, logit[i]);
#pragma unroll
        for (int off = 16; off; off >>= 1) m = fmaxf(m, __shfl_xor_sync(0xffffffffu, m, off));
        float sm = 0.f;
        for (int i = lane; i < OUT_SZ; i += 32) {
            float e = expf(logit[i] - m);
            logit[i] = e;
            sm += e;
        }
#pragma unroll
        for (int off = 16; off; off >>= 1) sm += __shfl_xor_sync(0xffffffffu, sm, off);
        if (lane == 0) red_sum = sm;
    }
    __syncthreads();
    float inv = 1.0f / red_sum;
    for (int i = tid; i < OUT_SZ; i += 128)
        out[(size_t)b * OUT_SZ + i] = logit[i] * inv;
}

// ---------------- launcher ----------------
extern "C" void kernel_launch(void* const* d_in, const int* in_sizes, int n_in,
                              void* d_out, int out_size) {
    const float* x     = (const float*)d_in[0];
    const float* W_in  = (const float*)d_in[1];
    const float* b_in  = (const float*)d_in[2];
    const float* W_lin = (const float*)d_in[3];
    const float* W_rec = (const float*)d_in[4];
    const float* b_rec = (const float*)d_in[5];
    const float* W_ro  = (const float*)d_in[6];
    const float* b_ro  = (const float*)d_in[7];

    float* out_main = (float*)d_out;
    float* spk_out  = nullptr;
    if (out_size >= OUT_ELEMS + SPK_ELEMS) {
        spk_out = (float*)d_out + OUT_ELEMS;          // (out, spk_rec) concatenated
    } else if (out_size == SPK_ELEMS) {
        spk_out = (float*)d_out;                       // only spk_rec compared
        out_main = nullptr;
    }
    // else: only `out` compared; spikes stay internal

    k_init<<<128, 256>>>();
    k_input_gemm<<<dim3(R_SZ / 128, (T_STEPS * B_SZ) / 128), 256>>>(x, W_in, b_in);

    for (int t = 0; t < T_STEPS; t++) {
        k_step_gemm<<<dim3(16, 2, 8), 256>>>(t, W_rec, W_lin);
        k_update<<<128, 256>>>(t, spk_out, b_rec);
    }

    k_ro_reduce<<<384, 256>>>();
    if (out_main) k_readout<<<B_SZ, 128>>>(out_main, W_ro, b_ro);
}